// round 16
// baseline (speedup 1.0000x reference)
#include <cuda_runtime.h>
#include <cuda_fp16.h>
#include <cstdint>

#define N 2048
#define E 4
#define C 4
#define F 128      // W_OUT
#define WIN 256
#define NNSZ ((size_t)N * N)
#define NFSZ ((size_t)N * F)
#define SPB_SCALE 1024.0f
#define SPB_UNSCALE (1.0f / 1024.0f)

// ---------------- scratch (static device globals; no allocation) ----------------
__device__ float g_fw[3][16];            // softmaxed weights: [0]=fw1, [1]=fw2, [2]=fw3
__device__ float g_support[N * F];       // X @ gcn_w              [n][f]
__device__ float g_part[16 * E * N];     // per-chunk partial raw rowsums
__device__ float g_v1[C * N];
__device__ float g_v2p[4][C * N];        // split-k partials of v2
__device__ float g_v3p[4][C * N];        // split-k partials of v3
__device__ float g_d[C * N];             // deg^-1/2
__device__ float g_Sp[C * N * F];        // diag(d)@support natural [c][n][f] fp32
// fp16 fragment-order planes
__device__ __align__(16) __half g_SpBH[C * N * F];   // B plane stage 0 (scaled x1024)
__device__ __align__(16) __half g_T0BH[C * N * F];   // B plane stage 1 (natural)
__device__ __align__(16) __half g_T1BH[C * N * F];   // B plane stage 2 (natural)
// RAW edge planes fp16 fragment order: [e], unit = m16 x k16 (256 halfs); unit = mt*128 + kt
__device__ __align__(16) __half g_ArH[4 * NNSZ];     // 32 MB — L2-resident

__device__ __forceinline__ uint32_t pkh(float a, float b) {
    __half2 h = __floats2half2_rn(a, b);
    return *(uint32_t*)&h;
}
__device__ __forceinline__ float2 h22(uint32_t u) {
    return __half22float2(*(__half2*)&u);
}
// mix 4 raw fp16 half2 components in fp32, repack fp16
__device__ __forceinline__ uint32_t mixc(uint32_t a0, uint32_t a1, uint32_t a2, uint32_t a3,
                                         float w0, float w1, float w2, float w3) {
    float2 f0 = h22(a0), f1 = h22(a1), f2 = h22(a2), f3 = h22(a3);
    return pkh(w0 * f0.x + w1 * f1.x + w2 * f2.x + w3 * f3.x,
               w0 * f0.y + w1 * f1.y + w2 * f2.y + w3 * f3.y);
}

// mma.m16n8k16 f16 -> f32 accum
__device__ __forceinline__ void mma_f16(float& d0, float& d1, float& d2, float& d3,
                                        uint32_t a0, uint32_t a1, uint32_t a2, uint32_t a3,
                                        uint32_t b0, uint32_t b1) {
    asm volatile(
        "mma.sync.aligned.m16n8k16.row.col.f32.f16.f16.f32 "
        "{%0,%1,%2,%3}, {%4,%5,%6,%7}, {%8,%9}, {%0,%1,%2,%3};"
        : "+f"(d0), "+f"(d1), "+f"(d2), "+f"(d3)
        : "r"(a0), "r"(a1), "r"(a2), "r"(a3), "r"(b0), "r"(b1));
}

__device__ __forceinline__ void cp_async16(uint32_t s, const void* g) {
    asm volatile("cp.async.ca.shared.global [%0], [%1], 16;" :: "r"(s), "l"(g));
}
__device__ __forceinline__ void cp_commit() { asm volatile("cp.async.commit_group;"); }
__device__ __forceinline__ void cp_wait1() { asm volatile("cp.async.wait_group 1;"); }
__device__ __forceinline__ void cp_wait0() { asm volatile("cp.async.wait_group 0;"); }

// ---------------- tiny: softmax of 4x4 weight rows ----------------
__global__ void k_softmax(const float* __restrict__ w1,
                          const float* __restrict__ w2,
                          const float* __restrict__ w3) {
    int t = threadIdx.x;
    if (t >= 12) return;
    int mat = t >> 2, row = t & 3;
    const float* src = (mat == 0) ? w1 : (mat == 1) ? w2 : w3;
    float a0 = src[row * 4 + 0], a1 = src[row * 4 + 1];
    float a2 = src[row * 4 + 2], a3 = src[row * 4 + 3];
    float mx = fmaxf(fmaxf(a0, a1), fmaxf(a2, a3));
    float e0 = expf(a0 - mx), e1 = expf(a1 - mx), e2 = expf(a2 - mx), e3 = expf(a3 - mx);
    float inv = 1.0f / (e0 + e1 + e2 + e3);
    g_fw[mat][row * 4 + 0] = e0 * inv;
    g_fw[mat][row * 4 + 1] = e1 * inv;
    g_fw[mat][row * 4 + 2] = e2 * inv;
    g_fw[mat][row * 4 + 3] = e3 * inv;
}

// ---------------- support = X @ gcn_w  (+ fused mix_v1 tail) ----------------
__global__ void __launch_bounds__(256) k_support(const float* __restrict__ X,
                                                 const float* __restrict__ W) {
    __shared__ float Xs[32][WIN];
    __shared__ float rsum[32][4];
    int tid = threadIdx.x;
    int row0 = blockIdx.x * 32;
    const float4* Xg = (const float4*)(X + (size_t)row0 * WIN);
    float4* Xs4 = (float4*)&Xs[0][0];
    #pragma unroll
    for (int j = 0; j < (32 * WIN / 4) / 256; j++)
        Xs4[tid + j * 256] = Xg[tid + j * 256];

    if (tid < 128) {
        int r = tid >> 2, e = tid & 3;
        float s = 0.f;
        #pragma unroll
        for (int ch = 0; ch < 16; ch++)
            s += g_part[(size_t)ch * (4 * N) + e * N + row0 + r];
        rsum[r][e] = s;
    }
    __syncthreads();
    if (tid < 32) {
        int r = tid;
        #pragma unroll
        for (int c = 0; c < 4; c++)
            g_v1[c * N + row0 + r] =
                g_fw[2][c * 4 + 0] * rsum[r][0] + g_fw[2][c * 4 + 1] * rsum[r][1]
              + g_fw[2][c * 4 + 2] * rsum[r][2] + g_fw[2][c * 4 + 3] * rsum[r][3];
    }

    int f = tid & 127, ty = tid >> 7;
    float acc[16];
    #pragma unroll
    for (int r = 0; r < 16; r++) acc[r] = 0.f;
    for (int k = 0; k < WIN; k++) {
        float w = W[k * F + f];
        #pragma unroll
        for (int r = 0; r < 16; r++)
            acc[r] = fmaf(Xs[ty * 16 + r][k], w, acc[r]);
    }
    #pragma unroll
    for (int r = 0; r < 16; r++)
        g_support[(size_t)(row0 + ty * 16 + r) * F + f] = acc[r];
}

// ---------------- fragraw fp16: raw A -> 4 fp16 frag planes + partial rowsums ----------------
// grid: (16 chunks, 128 bands), 256 threads.
__global__ void __launch_bounds__(256) k_fragraw_h(const float* __restrict__ A) {
    __shared__ float As[4][16][132];
    const int tid = threadIdx.x, lane = tid & 31, warp = tid >> 5;
    const int g = lane >> 2, cl = lane & 3;
    const int ch = blockIdx.x;
    const int band = blockIdx.y;
    const int n0 = band * 16, m0 = ch * 128;

    #pragma unroll
    for (int e = 0; e < 4; e++)
        #pragma unroll
        for (int j = 0; j < 2; j++) {
            int idx = tid + j * 256;
            int r = idx >> 5, m4 = idx & 31;
            *(float4*)&As[e][r][m4 * 4] =
                *(const float4*)(A + (size_t)e * NNSZ + (size_t)(n0 + r) * N + m0 + m4 * 4);
        }
    __syncthreads();

    {
        int e = tid >> 6, r = (tid >> 2) & 15, part = tid & 3;
        float s = 0.f;
        #pragma unroll
        for (int i = 0; i < 32; i++) s += As[e][r][part * 32 + i];
        s += __shfl_xor_sync(0xffffffffu, s, 1);
        s += __shfl_xor_sync(0xffffffffu, s, 2);
        if (part == 0) g_part[(size_t)ch * (4 * N) + e * N + n0 + r] = s;
    }

    // 4 planes x 8 k16-units = 32 warp tasks
    for (int task = warp; task < 32; task += 8) {
        int plane = task >> 3, ktl = task & 7;
        int cols[4] = {ktl * 16 + 2 * cl, ktl * 16 + 2 * cl + 1,
                       ktl * 16 + 2 * cl + 8, ktl * 16 + 2 * cl + 9};
        float m[8];
        #pragma unroll
        for (int j = 0; j < 4; j++) {
            m[j * 2]     = As[plane][g][cols[j]];
            m[j * 2 + 1] = As[plane][g + 8][cols[j]];
        }
        uint4 u;
        u.x = pkh(m[0], m[2]);
        u.y = pkh(m[1], m[3]);
        u.z = pkh(m[4], m[6]);
        u.w = pkh(m[5], m[7]);
        size_t unit = (size_t)band * 128 + ch * 8 + ktl;
        *(uint4*)(g_ArH + (size_t)plane * NNSZ + unit * 256 + lane * 8) = u;
    }
}

// ---------------- matvec on raw fp16 planes, mix-in-register, split-k ----------------
// stage0: w=fw2 (g_fw[1]), vin=v1 -> g_v2p ; stage1: w=fw1 (g_fw[0]), vin=Σv2p -> g_v3p
__global__ void __launch_bounds__(256) k_matvec_h(int stage) {
    __shared__ float vs[4][512];
    __shared__ float red[8][16][4];
    const int tid = threadIdx.x, lane = tid & 31, warp = tid >> 5;
    const int band = blockIdx.x, ks = blockIdx.y;
    const int g = lane >> 2, cl = lane & 3;

    if (stage == 0) {
        #pragma unroll
        for (int i = 0; i < 2; i++) {
            int idx = tid + i * 256;
            int c = idx >> 7, m4 = (idx & 127) * 4;
            *(float4*)&vs[c][m4] = *(const float4*)(g_v1 + c * N + ks * 512 + m4);
        }
    } else {
        #pragma unroll
        for (int i = 0; i < 2; i++) {
            int idx = tid + i * 256;
            int c = idx >> 7, m4 = (idx & 127) * 4;
            float4 s = *(const float4*)(g_v2p[0] + c * N + ks * 512 + m4);
            #pragma unroll
            for (int p = 1; p < 4; p++) {
                float4 t = *(const float4*)(g_v2p[p] + c * N + ks * 512 + m4);
                s.x += t.x; s.y += t.y; s.z += t.z; s.w += t.w;
            }
            *(float4*)&vs[c][m4] = s;
        }
    }
    float w[16];
    const float* wsrc = (stage == 0) ? g_fw[1] : g_fw[0];
    #pragma unroll
    for (int i = 0; i < 16; i++) w[i] = wsrc[i];
    __syncthreads();

    const uint4* __restrict__ P = (const uint4*)g_ArH;
    const size_t PST = NNSZ / 8;

    float acc0[4] = {0.f, 0.f, 0.f, 0.f};
    float acc1[4] = {0.f, 0.f, 0.f, 0.f};
    #pragma unroll
    for (int j = 0; j < 4; j++) {
        int ktl = warp * 4 + j;
        size_t bi = ((size_t)band * 128 + ks * 32 + ktl) * 32 + lane;
        int mL = ktl * 16 + 2 * cl;
        uint4 u0 = P[bi], u1 = P[bi + PST], u2 = P[bi + 2 * PST], u3 = P[bi + 3 * PST];
        float2 x0 = h22(u0.x), x1 = h22(u1.x), x2 = h22(u2.x), x3 = h22(u3.x);
        float2 y0 = h22(u0.y), y1 = h22(u1.y), y2 = h22(u2.y), y3 = h22(u3.y);
        float2 z0 = h22(u0.z), z1 = h22(u1.z), z2 = h22(u2.z), z3 = h22(u3.z);
        float2 q0 = h22(u0.w), q1 = h22(u1.w), q2 = h22(u2.w), q3 = h22(u3.w);
        #pragma unroll
        for (int c = 0; c < 4; c++) {
            float wa = w[c * 4], wb = w[c * 4 + 1], wc = w[c * 4 + 2], wd = w[c * 4 + 3];
            float mxx = wa * x0.x + wb * x1.x + wc * x2.x + wd * x3.x;
            float mxy = wa * x0.y + wb * x1.y + wc * x2.y + wd * x3.y;
            float myx = wa * y0.x + wb * y1.x + wc * y2.x + wd * y3.x;
            float myy = wa * y0.y + wb * y1.y + wc * y2.y + wd * y3.y;
            float mzx = wa * z0.x + wb * z1.x + wc * z2.x + wd * z3.x;
            float mzy = wa * z0.y + wb * z1.y + wc * z2.y + wd * z3.y;
            float mqx = wa * q0.x + wb * q1.x + wc * q2.x + wd * q3.x;
            float mqy = wa * q0.y + wb * q1.y + wc * q2.y + wd * q3.y;
            float vx = vs[c][mL], vy = vs[c][mL + 1];
            float vz = vs[c][mL + 8], vw = vs[c][mL + 9];
            acc0[c] += mxx * vx + mxy * vy + mzx * vz + mzy * vw;
            acc1[c] += myx * vx + myy * vy + mqx * vz + mqy * vw;
        }
    }
    #pragma unroll
    for (int d = 1; d <= 2; d <<= 1)
        #pragma unroll
        for (int c = 0; c < 4; c++) {
            acc0[c] += __shfl_xor_sync(0xffffffffu, acc0[c], d);
            acc1[c] += __shfl_xor_sync(0xffffffffu, acc1[c], d);
        }
    if (cl == 0) {
        #pragma unroll
        for (int c = 0; c < 4; c++) {
            red[warp][g][c] = acc0[c];
            red[warp][g + 8][c] = acc1[c];
        }
    }
    __syncthreads();
    float* vout = (stage == 0) ? g_v2p[ks] : g_v3p[ks];
    if (tid < 64) {
        int row = tid >> 2, c = tid & 3;
        float s = 0.f;
        #pragma unroll
        for (int wv = 0; wv < 8; wv++) s += red[wv][row][c];
        vout[c * N + band * 16 + row] = s;
    }
}

// ---------------- d, Sp natural fp32, SpB fp16 scaled (fragment B-units) ----------------
__global__ void __launch_bounds__(256) k_dSp_h() {
    __shared__ float sup[16][132];
    __shared__ float dsm[4][16];
    const int tid = threadIdx.x;
    const int k0 = blockIdx.x * 16;
    {
        int r = tid >> 4, f8 = (tid & 15) * 8;
        *(float4*)&sup[r][f8] = *(const float4*)(g_support + (size_t)(k0 + r) * F + f8);
        *(float4*)&sup[r][f8 + 4] = *(const float4*)(g_support + (size_t)(k0 + r) * F + f8 + 4);
    }
    if (tid < 64) {
        int c = tid >> 4, kk = tid & 15;
        float v3 = g_v3p[0][c * N + k0 + kk] + g_v3p[1][c * N + k0 + kk]
                 + g_v3p[2][c * N + k0 + kk] + g_v3p[3][c * N + k0 + kk];
        float deg = v3 + 1.0f;
        float d = (deg > 0.f) ? rsqrtf(deg) : 0.f;
        dsm[c][kk] = d;
        g_d[c * N + k0 + kk] = d;
    }
    __syncthreads();
    {
        int r = tid >> 4, f8 = (tid & 15) * 8;
        float4 s0 = *(float4*)&sup[r][f8];
        float4 s1 = *(float4*)&sup[r][f8 + 4];
        #pragma unroll
        for (int c = 0; c < 4; c++) {
            float d = dsm[c][r];
            float4 o0 = make_float4(d * s0.x, d * s0.y, d * s0.z, d * s0.w);
            float4 o1 = make_float4(d * s1.x, d * s1.y, d * s1.z, d * s1.w);
            *(float4*)(g_Sp + ((size_t)c * N + k0 + r) * F + f8) = o0;
            *(float4*)(g_Sp + ((size_t)c * N + k0 + r) * F + f8 + 4) = o1;
        }
    }
    {
        int nt = tid >> 5, l = tid & 31;
        int g = l >> 2, cl = l & 3;
        int na = nt * 16 + g, nb = na + 8;
        int ka = 2 * cl, kb = 2 * cl + 8;
        #pragma unroll
        for (int c = 0; c < 4; c++) {
            float d0 = dsm[c][ka] * SPB_SCALE,     d1 = dsm[c][ka + 1] * SPB_SCALE;
            float d8 = dsm[c][kb] * SPB_SCALE,     d9 = dsm[c][kb + 1] * SPB_SCALE;
            uint4 u;
            u.x = pkh(d0 * sup[ka][na], d1 * sup[ka + 1][na]);
            u.y = pkh(d8 * sup[kb][na], d9 * sup[kb + 1][na]);
            u.z = pkh(d0 * sup[ka][nb], d1 * sup[ka + 1][nb]);
            u.w = pkh(d8 * sup[kb][nb], d9 * sup[kb + 1][nb]);
            *(uint4*)(g_SpBH + (size_t)c * NFSZ + ((size_t)blockIdx.x * 8 + nt) * 256 + l * 8) = u;
        }
    }
}

// ---------------- main GEMM: raw A planes + in-register mix, fp16 mma, cp.async depth 3 ----------------
// Group = 4 kt16 x (4 raw-A-planes x 4 m-units + 8 n-units) x 32 uint4 = 3072 uint4 (48 KB).
// 3 buffers = 144 KB. 256 threads, 8 warps, warp tile 32x32. grid (32, 4).
#define GQ2 3072
#define GEMM_SMEM (3 * GQ2 * 16)

__global__ void __launch_bounds__(256) k_gemm_hp(const float* __restrict__ bias,
                                                 float* __restrict__ out, int stage) {
    extern __shared__ uint4 smp[];
    const int tid = threadIdx.x, lane = tid & 31, warp = tid >> 5;
    const int wm = warp >> 2, wn = warp & 3;       // 2 x 4 warps, warp tile 32x32
    const int c = blockIdx.y;
    const int bx = blockIdx.x;
    const int n0 = bx * 64;
    const int g = lane >> 2, cl = lane & 3;

    const float* wsrc = (stage == 0) ? g_fw[2] : (stage == 1) ? g_fw[1] : g_fw[0];
    const float w0 = wsrc[c * 4 + 0], w1 = wsrc[c * 4 + 1];
    const float w2 = wsrc[c * 4 + 2], w3 = wsrc[c * 4 + 3];

    const uint4* __restrict__ Araw = (const uint4*)g_ArH;   // 4 planes, PST apart
    const size_t PST = NNSZ / 8;
    const uint4* __restrict__ Bplane = (const uint4*)(((stage == 0) ? g_SpBH :
                                        (stage == 1) ? g_T0BH : g_T1BH) + (size_t)c * NFSZ);
    const uint32_t sbase = (uint32_t)__cvta_generic_to_shared(smp);

    float acc[2][4][4];
    #pragma unroll
    for (int i = 0; i < 2; i++)
        #pragma unroll
        for (int j = 0; j < 4; j++)
            #pragma unroll
            for (int q = 0; q < 4; q++) acc[i][j][q] = 0.f;

    // prologue: groups 0,1
    #pragma unroll
    for (int p = 0; p < 2; p++) {
        uint32_t gb = sbase + (uint32_t)(p * GQ2) * 16;
        #pragma unroll
        for (int q = 0; q < 8; q++) {          // A: 4 planes x 4 kt x 4 mu
            int idx = tid + q * 256;
            int e = idx >> 9, ktl = (idx >> 7) & 3, mu = (idx >> 5) & 3, ln = idx & 31;
            cp_async16(gb + (uint32_t)(((e * 4 + ktl) * 4 + mu) * 32 + ln) * 16,
                       Araw + (size_t)e * PST
                            + ((size_t)(bx * 4 + mu) * 128 + (size_t)(4 * p + ktl)) * 32 + ln);
        }
        #pragma unroll
        for (int q = 0; q < 4; q++) {          // B
            int idx = tid + q * 256;
            int ktl = idx >> 8, nu = (idx >> 5) & 7, ln = idx & 31;
            cp_async16(gb + (uint32_t)(2048 + (ktl * 8 + nu) * 32 + ln) * 16,
                       Bplane + ((size_t)(4 * p + ktl) * 8 + nu) * 32 + ln);
        }
        cp_commit();
    }

    int buf = 0, pbuf = 2;
    for (int gr = 0; gr < 32; gr++) {
        cp_wait1();
        __syncthreads();
        if (gr + 2 < 32) {
            uint32_t gb = sbase + (uint32_t)(pbuf * GQ2) * 16;
            #pragma unroll
            for (int q = 0; q < 8; q++) {
                int idx = tid + q * 256;
                int e = idx >> 9, ktl = (idx >> 7) & 3, mu = (idx >> 5) & 3, ln = idx & 31;
                cp_async16(gb + (uint32_t)(((e * 4 + ktl) * 4 + mu) * 32 + ln) * 16,
                           Araw + (size_t)e * PST
                                + ((size_t)(bx * 4 + mu) * 128 + (size_t)(4 * (gr + 2) + ktl)) * 32 + ln);
            }
            #pragma unroll
            for (int q = 0; q < 4; q++) {
                int idx = tid + q * 256;
                int ktl = idx >> 8, nu = (idx >> 5) & 7, ln = idx & 31;
                cp_async16(gb + (uint32_t)(2048 + (ktl * 8 + nu) * 32 + ln) * 16,
                           Bplane + ((size_t)(4 * (gr + 2) + ktl) * 8 + nu) * 32 + ln);
            }
        }
        cp_commit();

        const uint4* Ab = smp + (size_t)buf * GQ2;
        const uint4* Bb = Ab + 2048;
        #pragma unroll
        for (int j = 0; j < 4; j++) {
            uint4 b0 = Bb[(j * 8 + wn * 2) * 32 + lane];
            uint4 b1 = Bb[(j * 8 + wn * 2 + 1) * 32 + lane];
            #pragma unroll
            for (int i = 0; i < 2; i++) {
                int base = (j * 4 + wm * 2 + i) * 32 + lane;
                uint4 r0 = Ab[base];
                uint4 r1 = Ab[base + 512];
                uint4 r2 = Ab[base + 1024];
                uint4 r3 = Ab[base + 1536];
                uint32_t ax = mixc(r0.x, r1.x, r2.x, r3.x, w0, w1, w2, w3);
                uint32_t ay = mixc(r0.y, r1.y, r2.y, r3.y, w0, w1, w2, w3);
                uint32_t az = mixc(r0.z, r1.z, r2.z, r3.z, w0, w1, w2, w3);
                uint32_t aw = mixc(r0.w, r1.w, r2.w, r3.w, w0, w1, w2, w3);
                mma_f16(acc[i][0][0], acc[i][0][1], acc[i][0][2], acc[i][0][3],
                        ax, ay, az, aw, b0.x, b0.y);
                mma_f16(acc[i][1][0], acc[i][1][1], acc[i][1][2], acc[i][1][3],
                        ax, ay, az, aw, b0.z, b0.w);
                mma_f16(acc[i][2][0], acc[i][2][1], acc[i][2][2], acc[i][2][3],
                        ax, ay, az, aw, b1.x, b1.y);
                mma_f16(acc[i][3][0], acc[i][3][1], acc[i][3][2], acc[i][3][3],
                        ax, ay, az, aw, b1.z, b1.w);
            }
        }
        buf = (buf + 1 == 3) ? 0 : buf + 1;
        pbuf = (pbuf + 1 == 3) ? 0 : pbuf + 1;
    }

    cp_wait0();
    __syncthreads();

    // park D in smem (natural [node][f]) — reuse pipeline smem
    float* smf = (float*)smp;
    {
        #pragma unroll
        for (int i = 0; i < 2; i++)
            #pragma unroll
            for (int j = 0; j < 4; j++) {
                int row = wm * 32 + i * 16 + g;
                int col = wn * 32 + j * 8 + 2 * cl;
                smf[row * 132 + col] = acc[i][j][0];
                smf[row * 132 + col + 1] = acc[i][j][1];
                smf[(row + 8) * 132 + col] = acc[i][j][2];
                smf[(row + 8) * 132 + col + 1] = acc[i][j][3];
            }
    }
    __syncthreads();

    if (stage < 2) {
        const float scl = (stage == 0) ? SPB_UNSCALE : 1.0f;
        __half* __restrict__ Bout = ((stage == 0) ? g_T0BH : g_T1BH) + (size_t)c * NFSZ;
        #pragma unroll
        for (int q = 0; q < 4; q++) {
            int uu = warp * 4 + q;
            int ku = uu >> 3, nu = uu & 7;
            int kb2 = ku * 16;
            int na = nu * 16 + g, nb = na + 8;
            int ka = kb2 + 2 * cl, kc = kb2 + 2 * cl + 8;
            uint4 u;
            u.x = pkh(scl * smf[ka * 132 + na],     scl * smf[(ka + 1) * 132 + na]);
            u.y = pkh(scl * smf[kc * 132 + na],     scl * smf[(kc + 1) * 132 + na]);
            u.z = pkh(scl * smf[ka * 132 + nb],     scl * smf[(ka + 1) * 132 + nb]);
            u.w = pkh(scl * smf[kc * 132 + nb],     scl * smf[(kc + 1) * 132 + nb]);
            *(uint4*)(Bout + ((size_t)(bx * 4 + ku) * 8 + nu) * 256 + lane * 8) = u;
        }
    } else {
        const int r = tid >> 2;
        const int fc = (tid & 3) * 32;
        const int node = n0 + r;
        const float dd = g_d[c * N + node];
        const float* sp = g_Sp + ((size_t)(c * N + node)) * F;
        float* op = out + (size_t)node * (C * F) + c * F;
        #pragma unroll
        for (int j0 = 0; j0 < 32; j0 += 4) {
            float4 a4 = *(float4*)&smf[r * 132 + fc + j0];
            float4 s4 = *(const float4*)(sp + fc + j0);
            float4 b4 = *(const float4*)(bias + fc + j0);
            float4 o;
            o.x = fmaxf(dd * (a4.x + s4.x) + b4.x, 0.f);
            o.y = fmaxf(dd * (a4.y + s4.y) + b4.y, 0.f);
            o.z = fmaxf(dd * (a4.z + s4.z) + b4.z, 0.f);
            o.w = fmaxf(dd * (a4.w + s4.w) + b4.w, 0.f);
            *(float4*)(op + fc + j0) = o;
        }
    }
}

// ---------------- launcher ----------------
extern "C" void kernel_launch(void* const* d_in, const int* in_sizes, int n_in,
                              void* d_out, int out_size) {
    const float* A  = (const float*)d_in[0];   // [E,N,N]
    const float* X  = (const float*)d_in[1];   // [N,WIN]
    const float* w1 = (const float*)d_in[2];   // [C,E]
    const float* w2 = (const float*)d_in[3];   // [C,E]
    const float* w3 = (const float*)d_in[4];   // [C,C]
    const float* gw = (const float*)d_in[5];   // [WIN,F]
    const float* gb = (const float*)d_in[6];   // [F]
    float* out = (float*)d_out;                // [N, C*F]

    static bool attr_done = false;
    if (!attr_done) {
        cudaFuncSetAttribute(k_gemm_hp, cudaFuncAttributeMaxDynamicSharedMemorySize,
                             GEMM_SMEM);
        attr_done = true;
    }

    k_softmax<<<1, 32>>>(w1, w2, w3);
    k_fragraw_h<<<dim3(16, 128), 256>>>(A);      // 4 raw fp16 frag planes + partial rowsums
    k_support<<<N / 32, 256>>>(X, gw);           // support + fused mix_v1
    k_matvec_h<<<dim3(128, 4), 256>>>(0);        // v2 partials (raw planes + mix)
    k_matvec_h<<<dim3(128, 4), 256>>>(1);        // v3 partials
    k_dSp_h<<<N / 16, 256>>>();                  // d, Sp, SpB
    k_gemm_hp<<<dim3(N / 64, C), 256, GEMM_SMEM>>>(gb, out, 0);   // T0B
    k_gemm_hp<<<dim3(N / 64, C), 256, GEMM_SMEM>>>(gb, out, 1);   // T1B
    k_gemm_hp<<<dim3(N / 64, C), 256, GEMM_SMEM>>>(gb, out, 2);   // out
}

// round 17
// speedup vs baseline: 2.1017x; 2.1017x over previous
#include <cuda_runtime.h>
#include <cuda_fp16.h>
#include <cstdint>

#define N 2048
#define E 4
#define C 4
#define F 128      // W_OUT
#define WIN 256
#define NNSZ ((size_t)N * N)
#define NFSZ ((size_t)N * F)
#define SPB_SCALE 1024.0f
#define SPB_UNSCALE (1.0f / 1024.0f)

// ---------------- scratch (static device globals; no allocation) ----------------
__device__ float g_fw[3][16];            // softmaxed weights: [0]=fw1, [1]=fw2, [2]=fw3
__device__ float g_support[N * F];       // X @ gcn_w              [n][f]
__device__ float g_part[16 * E * N];     // per-chunk partial rowsums
__device__ float g_v1[C * N];
__device__ float g_v2p[4][C * N];        // split-k partials of v2
__device__ float g_v3p[4][C * N];        // split-k partials of v3
__device__ float g_d[C * N];             // deg^-1/2
__device__ float g_Sp[C * N * F];        // diag(d)@support natural [c][n][f] fp32
// fp16 fragment-order planes
__device__ __align__(16) __half g_SpBH[C * N * F];   // B plane stage 0 (scaled x1024)
__device__ __align__(16) __half g_T0BH[C * N * F];   // B plane stage 1 (natural)
__device__ __align__(16) __half g_T1BH[C * N * F];   // B plane stage 2 (natural)
// premixed A planes fp16: [stage*4+c], unit = m16 x k16 (256 halfs); unit idx = mt*128 + kt
__device__ __align__(16) __half g_AmH[12 * NNSZ];    // 96 MB

__device__ __forceinline__ uint32_t pkh(float a, float b) {
    __half2 h = __floats2half2_rn(a, b);
    return *(uint32_t*)&h;
}

__device__ __forceinline__ uint32_t mix_h2(__half2 a0, __half2 a1, __half2 a2, __half2 a3,
                                           float w0, float w1, float w2, float w3) {
    float2 f0 = __half22float2(a0), f1 = __half22float2(a1);
    float2 f2 = __half22float2(a2), f3 = __half22float2(a3);
    return pkh(w0 * f0.x + w1 * f1.x + w2 * f2.x + w3 * f3.x,
               w0 * f0.y + w1 * f1.y + w2 * f2.y + w3 * f3.y);
}

// mma.m16n8k16 f16 -> f32 accum
__device__ __forceinline__ void mma_f16(float& d0, float& d1, float& d2, float& d3,
                                        uint32_t a0, uint32_t a1, uint32_t a2, uint32_t a3,
                                        uint32_t b0, uint32_t b1) {
    asm volatile(
        "mma.sync.aligned.m16n8k16.row.col.f32.f16.f16.f32 "
        "{%0,%1,%2,%3}, {%4,%5,%6,%7}, {%8,%9}, {%0,%1,%2,%3};"
        : "+f"(d0), "+f"(d1), "+f"(d2), "+f"(d3)
        : "r"(a0), "r"(a1), "r"(a2), "r"(a3), "r"(b0), "r"(b1));
}

__device__ __forceinline__ void cp_async16(uint32_t s, const void* g) {
    asm volatile("cp.async.ca.shared.global [%0], [%1], 16;" :: "r"(s), "l"(g));
}
__device__ __forceinline__ void cp_commit() { asm volatile("cp.async.commit_group;"); }
__device__ __forceinline__ void cp_wait2() { asm volatile("cp.async.wait_group 2;"); }
__device__ __forceinline__ void cp_wait0() { asm volatile("cp.async.wait_group 0;"); }

// ---------------- tiny: softmax of 4x4 weight rows ----------------
__global__ void k_softmax(const float* __restrict__ w1,
                          const float* __restrict__ w2,
                          const float* __restrict__ w3) {
    int t = threadIdx.x;
    if (t >= 12) return;
    int mat = t >> 2, row = t & 3;
    const float* src = (mat == 0) ? w1 : (mat == 1) ? w2 : w3;
    float a0 = src[row * 4 + 0], a1 = src[row * 4 + 1];
    float a2 = src[row * 4 + 2], a3 = src[row * 4 + 3];
    float mx = fmaxf(fmaxf(a0, a1), fmaxf(a2, a3));
    float e0 = expf(a0 - mx), e1 = expf(a1 - mx), e2 = expf(a2 - mx), e3 = expf(a3 - mx);
    float inv = 1.0f / (e0 + e1 + e2 + e3);
    g_fw[mat][row * 4 + 0] = e0 * inv;
    g_fw[mat][row * 4 + 1] = e1 * inv;
    g_fw[mat][row * 4 + 2] = e2 * inv;
    g_fw[mat][row * 4 + 3] = e3 * inv;
}

// ---------------- support = X @ gcn_w  (+ fused mix_v1 tail) ----------------
__global__ void __launch_bounds__(256) k_support(const float* __restrict__ X,
                                                 const float* __restrict__ W) {
    __shared__ float Xs[32][WIN];
    __shared__ float rsum[32][4];
    int tid = threadIdx.x;
    int row0 = blockIdx.x * 32;
    const float4* Xg = (const float4*)(X + (size_t)row0 * WIN);
    float4* Xs4 = (float4*)&Xs[0][0];
    #pragma unroll
    for (int j = 0; j < (32 * WIN / 4) / 256; j++)
        Xs4[tid + j * 256] = Xg[tid + j * 256];

    if (tid < 128) {
        int r = tid >> 2, e = tid & 3;
        float s = 0.f;
        #pragma unroll
        for (int ch = 0; ch < 16; ch++)
            s += g_part[(size_t)ch * (4 * N) + e * N + row0 + r];
        rsum[r][e] = s;
    }
    __syncthreads();
    if (tid < 32) {
        int r = tid;
        #pragma unroll
        for (int c = 0; c < 4; c++)
            g_v1[c * N + row0 + r] =
                g_fw[2][c * 4 + 0] * rsum[r][0] + g_fw[2][c * 4 + 1] * rsum[r][1]
              + g_fw[2][c * 4 + 2] * rsum[r][2] + g_fw[2][c * 4 + 3] * rsum[r][3];
    }

    int f = tid & 127, ty = tid >> 7;
    float acc[16];
    #pragma unroll
    for (int r = 0; r < 16; r++) acc[r] = 0.f;
    for (int k = 0; k < WIN; k++) {
        float w = W[k * F + f];
        #pragma unroll
        for (int r = 0; r < 16; r++)
            acc[r] = fmaf(Xs[ty * 16 + r][k], w, acc[r]);
    }
    #pragma unroll
    for (int r = 0; r < 16; r++)
        g_support[(size_t)(row0 + ty * 16 + r) * F + f] = acc[r];
}

// ---------------- premix fp16 (lean): fp16 smem staging, conflict-free frag reads ----------------
// grid: (16 chunks, 128 bands), 256 threads. 12 fp16 frag planes + partial rowsums.
// Ah[e][row][colpair] half2 with pad 68: frag-read bank = (4g+cl)&31, conflict-free.
__global__ void __launch_bounds__(256) k_premix_h(const float* __restrict__ A) {
    __shared__ __half2 Ah[4][16][68];   // 17.4 KB
    __shared__ float wsm[48];
    const int tid = threadIdx.x, lane = tid & 31, warp = tid >> 5;
    const int g = lane >> 2, cl = lane & 3;
    const int ch = blockIdx.x;            // 0..15 (128-col chunk)
    const int band = blockIdx.y;          // 0..127 (16-row band)
    const int n0 = band * 16, m0 = ch * 128;

    if (tid < 48) wsm[tid] = ((const float*)g_fw)[tid];
    #pragma unroll
    for (int e = 0; e < 4; e++)
        #pragma unroll
        for (int j = 0; j < 2; j++) {
            int idx = tid + j * 256;
            int r = idx >> 5, m4 = idx & 31;
            float4 v = *(const float4*)(A + (size_t)e * NNSZ + (size_t)(n0 + r) * N + m0 + m4 * 4);
            __half2 h0 = __floats2half2_rn(v.x, v.y);
            __half2 h1 = __floats2half2_rn(v.z, v.w);
            *(uint2*)&Ah[e][r][m4 * 2] = make_uint2(*(uint32_t*)&h0, *(uint32_t*)&h1);
        }
    __syncthreads();

    // partial rowsums (fp16-rounded elements) -> g_part[ch][e][n]
    {
        int e = tid >> 6, r = (tid >> 2) & 15, part = tid & 3;
        float s = 0.f;
        #pragma unroll
        for (int i = 0; i < 16; i++) {
            float2 f = __half22float2(Ah[e][r][part * 16 + i]);
            s += f.x + f.y;
        }
        s += __shfl_xor_sync(0xffffffffu, s, 1);
        s += __shfl_xor_sync(0xffffffffu, s, 2);
        if (part == 0) g_part[(size_t)ch * (4 * N) + e * N + n0 + r] = s;
    }

    // 12 planes x 8 k16-units = 96 warp tasks
    for (int task = warp; task < 96; task += 8) {
        int plane = task >> 3, ktl = task & 7;
        int s = plane >> 2;
        const float* wv = wsm + (2 - s) * 16 + (plane & 3) * 4;
        float w0 = wv[0], w1 = wv[1], w2 = wv[2], w3 = wv[3];
        int cpA = ktl * 8 + cl;          // colpair for u.x/u.y
        int cpB = cpA + 4;               // colpair for u.z/u.w
        uint4 u;
        u.x = mix_h2(Ah[0][g][cpA],     Ah[1][g][cpA],     Ah[2][g][cpA],     Ah[3][g][cpA],     w0, w1, w2, w3);
        u.y = mix_h2(Ah[0][g + 8][cpA], Ah[1][g + 8][cpA], Ah[2][g + 8][cpA], Ah[3][g + 8][cpA], w0, w1, w2, w3);
        u.z = mix_h2(Ah[0][g][cpB],     Ah[1][g][cpB],     Ah[2][g][cpB],     Ah[3][g][cpB],     w0, w1, w2, w3);
        u.w = mix_h2(Ah[0][g + 8][cpB], Ah[1][g + 8][cpB], Ah[2][g + 8][cpB], Ah[3][g + 8][cpB], w0, w1, w2, w3);
        size_t unit = (size_t)band * 128 + ch * 8 + ktl;
        *(uint4*)(g_AmH + (size_t)plane * NNSZ + unit * 256 + lane * 8) = u;
    }
}

// ---------------- matvec on fp16 premixed planes, split-k ----------------
__global__ void __launch_bounds__(256) k_matvec_h(int stage) {
    __shared__ float vs[4][512];
    __shared__ float red[8][16][4];
    const int tid = threadIdx.x, lane = tid & 31, warp = tid >> 5;
    const int band = blockIdx.x, ks = blockIdx.y;
    const int g = lane >> 2, cl = lane & 3;

    if (stage == 0) {
        #pragma unroll
        for (int i = 0; i < 2; i++) {
            int idx = tid + i * 256;
            int c = idx >> 7, m4 = (idx & 127) * 4;
            *(float4*)&vs[c][m4] = *(const float4*)(g_v1 + c * N + ks * 512 + m4);
        }
    } else {
        #pragma unroll
        for (int i = 0; i < 2; i++) {
            int idx = tid + i * 256;
            int c = idx >> 7, m4 = (idx & 127) * 4;
            float4 s = *(const float4*)(g_v2p[0] + c * N + ks * 512 + m4);
            #pragma unroll
            for (int p = 1; p < 4; p++) {
                float4 t = *(const float4*)(g_v2p[p] + c * N + ks * 512 + m4);
                s.x += t.x; s.y += t.y; s.z += t.z; s.w += t.w;
            }
            *(float4*)&vs[c][m4] = s;
        }
    }
    __syncthreads();

    const uint4* __restrict__ P = (const uint4*)(g_AmH + (size_t)(stage + 1) * 4 * NNSZ);
    const size_t PST = NNSZ / 8;

    float acc0[4] = {0.f, 0.f, 0.f, 0.f};
    float acc1[4] = {0.f, 0.f, 0.f, 0.f};
    #pragma unroll
    for (int j = 0; j < 4; j++) {
        int ktl = warp * 4 + j;
        size_t bi = ((size_t)band * 128 + ks * 32 + ktl) * 32 + lane;
        int mL = ktl * 16 + 2 * cl;
        #pragma unroll
        for (int c = 0; c < 4; c++) {
            uint4 u = P[bi + (size_t)c * PST];
            float vx = vs[c][mL], vy = vs[c][mL + 1];
            float vz = vs[c][mL + 8], vw = vs[c][mL + 9];
            float2 hx = __half22float2(*(__half2*)&u.x);
            float2 hy = __half22float2(*(__half2*)&u.y);
            float2 hz = __half22float2(*(__half2*)&u.z);
            float2 hw = __half22float2(*(__half2*)&u.w);
            acc0[c] = fmaf(hx.x, vx, fmaf(hx.y, vy, fmaf(hz.x, vz, fmaf(hz.y, vw, acc0[c]))));
            acc1[c] = fmaf(hy.x, vx, fmaf(hy.y, vy, fmaf(hw.x, vz, fmaf(hw.y, vw, acc1[c]))));
        }
    }
    #pragma unroll
    for (int d = 1; d <= 2; d <<= 1)
        #pragma unroll
        for (int c = 0; c < 4; c++) {
            acc0[c] += __shfl_xor_sync(0xffffffffu, acc0[c], d);
            acc1[c] += __shfl_xor_sync(0xffffffffu, acc1[c], d);
        }
    if (cl == 0) {
        #pragma unroll
        for (int c = 0; c < 4; c++) {
            red[warp][g][c] = acc0[c];
            red[warp][g + 8][c] = acc1[c];
        }
    }
    __syncthreads();
    float* vout = (stage == 0) ? g_v2p[ks] : g_v3p[ks];
    if (tid < 64) {
        int row = tid >> 2, c = tid & 3;
        float s = 0.f;
        #pragma unroll
        for (int wv = 0; wv < 8; wv++) s += red[wv][row][c];
        vout[c * N + band * 16 + row] = s;
    }
}

// ---------------- d, Sp natural fp32, SpB fp16 scaled (fragment B-units) ----------------
__global__ void __launch_bounds__(256) k_dSp_h() {
    __shared__ float sup[16][132];
    __shared__ float dsm[4][16];
    const int tid = threadIdx.x;
    const int k0 = blockIdx.x * 16;
    {
        int r = tid >> 4, f8 = (tid & 15) * 8;
        *(float4*)&sup[r][f8] = *(const float4*)(g_support + (size_t)(k0 + r) * F + f8);
        *(float4*)&sup[r][f8 + 4] = *(const float4*)(g_support + (size_t)(k0 + r) * F + f8 + 4);
    }
    if (tid < 64) {
        int c = tid >> 4, kk = tid & 15;
        float v3 = g_v3p[0][c * N + k0 + kk] + g_v3p[1][c * N + k0 + kk]
                 + g_v3p[2][c * N + k0 + kk] + g_v3p[3][c * N + k0 + kk];
        float deg = v3 + 1.0f;
        float d = (deg > 0.f) ? rsqrtf(deg) : 0.f;
        dsm[c][kk] = d;
        g_d[c * N + k0 + kk] = d;
    }
    __syncthreads();
    {
        int r = tid >> 4, f8 = (tid & 15) * 8;
        float4 s0 = *(float4*)&sup[r][f8];
        float4 s1 = *(float4*)&sup[r][f8 + 4];
        #pragma unroll
        for (int c = 0; c < 4; c++) {
            float d = dsm[c][r];
            float4 o0 = make_float4(d * s0.x, d * s0.y, d * s0.z, d * s0.w);
            float4 o1 = make_float4(d * s1.x, d * s1.y, d * s1.z, d * s1.w);
            *(float4*)(g_Sp + ((size_t)c * N + k0 + r) * F + f8) = o0;
            *(float4*)(g_Sp + ((size_t)c * N + k0 + r) * F + f8 + 4) = o1;
        }
    }
    {
        int nt = tid >> 5, l = tid & 31;
        int g = l >> 2, cl = l & 3;
        int na = nt * 16 + g, nb = na + 8;
        int ka = 2 * cl, kb = 2 * cl + 8;
        #pragma unroll
        for (int c = 0; c < 4; c++) {
            float d0 = dsm[c][ka] * SPB_SCALE,     d1 = dsm[c][ka + 1] * SPB_SCALE;
            float d8 = dsm[c][kb] * SPB_SCALE,     d9 = dsm[c][kb + 1] * SPB_SCALE;
            uint4 u;
            u.x = pkh(d0 * sup[ka][na], d1 * sup[ka + 1][na]);
            u.y = pkh(d8 * sup[kb][na], d9 * sup[kb + 1][na]);
            u.z = pkh(d0 * sup[ka][nb], d1 * sup[ka + 1][nb]);
            u.w = pkh(d8 * sup[kb][nb], d9 * sup[kb + 1][nb]);
            *(uint4*)(g_SpBH + (size_t)c * NFSZ + ((size_t)blockIdx.x * 8 + nt) * 256 + l * 8) = u;
        }
    }
}

// ---------------- main GEMM: fp16 m16n8k16, 256 threads, warp tile 32x32 ----------------
// cp.async depth-4 x k64 groups (24 KB each, 96 KB total). grid (32, 4).
#define GQ 1536
#define GEMM_SMEM (4 * GQ * 16)

__global__ void __launch_bounds__(256) k_gemm_hp(const float* __restrict__ bias,
                                                 float* __restrict__ out, int stage) {
    extern __shared__ uint4 smp[];
    const int tid = threadIdx.x, lane = tid & 31, warp = tid >> 5;   // 8 warps
    const int wm = warp >> 2, wn = warp & 3;       // 2 x 4 warps, warp tile 32x32
    const int c = blockIdx.y;
    const int bx = blockIdx.x;
    const int n0 = bx * 64;
    const int g = lane >> 2, cl = lane & 3;

    const uint4* __restrict__ Aplane = (const uint4*)(g_AmH + (size_t)(stage * 4 + c) * NNSZ);
    const uint4* __restrict__ Bplane = (const uint4*)(((stage == 0) ? g_SpBH :
                                        (stage == 1) ? g_T0BH : g_T1BH) + (size_t)c * NFSZ);
    const uint32_t sbase = (uint32_t)__cvta_generic_to_shared(smp);

    float acc[2][4][4];
    #pragma unroll
    for (int i = 0; i < 2; i++)
        #pragma unroll
        for (int j = 0; j < 4; j++)
            #pragma unroll
            for (int q = 0; q < 4; q++) acc[i][j][q] = 0.f;

    #pragma unroll
    for (int p = 0; p < 3; p++) {
        uint32_t gb = sbase + (uint32_t)(p * GQ) * 16;
        #pragma unroll
        for (int q = 0; q < 2; q++) {
            int idx = tid + q * 256;
            int ktl = idx >> 7, mu = (idx >> 5) & 3, ln = idx & 31;
            cp_async16(gb + (uint32_t)((ktl * 4 + mu) * 32 + ln) * 16,
                       Aplane + ((size_t)(bx * 4 + mu) * 128 + (size_t)(4 * p + ktl)) * 32 + ln);
        }
        #pragma unroll
        for (int q = 0; q < 4; q++) {
            int idx = tid + q * 256;
            int ktl = idx >> 8, nu = (idx >> 5) & 7, ln = idx & 31;
            cp_async16(gb + (uint32_t)(512 + (ktl * 8 + nu) * 32 + ln) * 16,
                       Bplane + ((size_t)(4 * p + ktl) * 8 + nu) * 32 + ln);
        }
        cp_commit();
    }

    for (int gr = 0; gr < 32; gr++) {
        cp_wait2();
        __syncthreads();
        if (gr + 3 < 32) {
            uint32_t gb = sbase + (uint32_t)(((gr + 3) & 3) * GQ) * 16;
            #pragma unroll
            for (int q = 0; q < 2; q++) {
                int idx = tid + q * 256;
                int ktl = idx >> 7, mu = (idx >> 5) & 3, ln = idx & 31;
                cp_async16(gb + (uint32_t)((ktl * 4 + mu) * 32 + ln) * 16,
                           Aplane + ((size_t)(bx * 4 + mu) * 128 + (size_t)(4 * (gr + 3) + ktl)) * 32 + ln);
            }
            #pragma unroll
            for (int q = 0; q < 4; q++) {
                int idx = tid + q * 256;
                int ktl = idx >> 8, nu = (idx >> 5) & 7, ln = idx & 31;
                cp_async16(gb + (uint32_t)(512 + (ktl * 8 + nu) * 32 + ln) * 16,
                           Bplane + ((size_t)(4 * (gr + 3) + ktl) * 8 + nu) * 32 + ln);
            }
        }
        cp_commit();

        const uint4* Ab = smp + (size_t)(gr & 3) * GQ;
        const uint4* Bb = Ab + 512;
        #pragma unroll
        for (int j = 0; j < 4; j++) {
            uint4 a0 = Ab[(j * 4 + wm * 2) * 32 + lane];
            uint4 a1 = Ab[(j * 4 + wm * 2 + 1) * 32 + lane];
            uint4 b0 = Bb[(j * 8 + wn * 2) * 32 + lane];
            uint4 b1 = Bb[(j * 8 + wn * 2 + 1) * 32 + lane];
            #pragma unroll
            for (int i = 0; i < 2; i++) {
                uint4 a = (i == 0) ? a0 : a1;
                mma_f16(acc[i][0][0], acc[i][0][1], acc[i][0][2], acc[i][0][3],
                        a.x, a.y, a.z, a.w, b0.x, b0.y);
                mma_f16(acc[i][1][0], acc[i][1][1], acc[i][1][2], acc[i][1][3],
                        a.x, a.y, a.z, a.w, b0.z, b0.w);
                mma_f16(acc[i][2][0], acc[i][2][1], acc[i][2][2], acc[i][2][3],
                        a.x, a.y, a.z, a.w, b1.x, b1.y);
                mma_f16(acc[i][3][0], acc[i][3][1], acc[i][3][2], acc[i][3][3],
                        a.x, a.y, a.z, a.w, b1.z, b1.w);
            }
        }
    }

    cp_wait0();
    __syncthreads();

    float* smf = (float*)smp;
    {
        #pragma unroll
        for (int i = 0; i < 2; i++)
            #pragma unroll
            for (int j = 0; j < 4; j++) {
                int row = wm * 32 + i * 16 + g;
                int col = wn * 32 + j * 8 + 2 * cl;
                smf[row * 132 + col] = acc[i][j][0];
                smf[row * 132 + col + 1] = acc[i][j][1];
                smf[(row + 8) * 132 + col] = acc[i][j][2];
                smf[(row + 8) * 132 + col + 1] = acc[i][j][3];
            }
    }
    __syncthreads();

    if (stage < 2) {
        const float scl = (stage == 0) ? SPB_UNSCALE : 1.0f;
        __half* __restrict__ Bout = ((stage == 0) ? g_T0BH : g_T1BH) + (size_t)c * NFSZ;
        #pragma unroll
        for (int q = 0; q < 4; q++) {
            int uu = warp * 4 + q;
            int ku = uu >> 3, nu = uu & 7;
            int kb2 = ku * 16;
            int na = nu * 16 + g, nb = na + 8;
            int ka = kb2 + 2 * cl, kc = kb2 + 2 * cl + 8;
            uint4 u;
            u.x = pkh(scl * smf[ka * 132 + na],     scl * smf[(ka + 1) * 132 + na]);
            u.y = pkh(scl * smf[kc * 132 + na],     scl * smf[(kc + 1) * 132 + na]);
            u.z = pkh(scl * smf[ka * 132 + nb],     scl * smf[(ka + 1) * 132 + nb]);
            u.w = pkh(scl * smf[kc * 132 + nb],     scl * smf[(kc + 1) * 132 + nb]);
            *(uint4*)(Bout + ((size_t)(bx * 4 + ku) * 8 + nu) * 256 + lane * 8) = u;
        }
    } else {
        const int r = tid >> 2;
        const int fc = (tid & 3) * 32;
        const int node = n0 + r;
        const float dd = g_d[c * N + node];
        const float* sp = g_Sp + ((size_t)(c * N + node)) * F;
        float* op = out + (size_t)node * (C * F) + c * F;
        #pragma unroll
        for (int j0 = 0; j0 < 32; j0 += 4) {
            float4 a4 = *(float4*)&smf[r * 132 + fc + j0];
            float4 s4 = *(const float4*)(sp + fc + j0);
            float4 b4 = *(const float4*)(bias + fc + j0);
            float4 o;
            o.x = fmaxf(dd * (a4.x + s4.x) + b4.x, 0.f);
            o.y = fmaxf(dd * (a4.y + s4.y) + b4.y, 0.f);
            o.z = fmaxf(dd * (a4.z + s4.z) + b4.z, 0.f);
            o.w = fmaxf(dd * (a4.w + s4.w) + b4.w, 0.f);
            *(float4*)(op + fc + j0) = o;
        }
    }
}

// ---------------- launcher ----------------
extern "C" void kernel_launch(void* const* d_in, const int* in_sizes, int n_in,
                              void* d_out, int out_size) {
    const float* A  = (const float*)d_in[0];   // [E,N,N]
    const float* X  = (const float*)d_in[1];   // [N,WIN]
    const float* w1 = (const float*)d_in[2];   // [C,E]
    const float* w2 = (const float*)d_in[3];   // [C,E]
    const float* w3 = (const float*)d_in[4];   // [C,C]
    const float* gw = (const float*)d_in[5];   // [WIN,F]
    const float* gb = (const float*)d_in[6];   // [F]
    float* out = (float*)d_out;                // [N, C*F]

    static bool attr_done = false;
    if (!attr_done) {
        cudaFuncSetAttribute(k_gemm_hp, cudaFuncAttributeMaxDynamicSharedMemorySize,
                             GEMM_SMEM);
        attr_done = true;
    }

    k_softmax<<<1, 32>>>(w1, w2, w3);
    k_premix_h<<<dim3(16, 128), 256>>>(A);       // 12 fp16 frag planes + partial rowsums
    k_support<<<N / 32, 256>>>(X, gw);           // support + fused mix_v1
    k_matvec_h<<<dim3(128, 4), 256>>>(0);        // v2 partials
    k_matvec_h<<<dim3(128, 4), 256>>>(1);        // v3 partials
    k_dSp_h<<<N / 16, 256>>>();                  // d, Sp, SpB
    k_gemm_hp<<<dim3(N / 64, C), 256, GEMM_SMEM>>>(gb, out, 0);   // T0B
    k_gemm_hp<<<dim3(N / 64, C), 256, GEMM_SMEM>>>(gb, out, 1);   // T1B
    k_gemm_hp<<<dim3(N / 64, C), 256, GEMM_SMEM>>>(gb, out, 2);   // out
}